// round 2
// baseline (speedup 1.0000x reference)
#include <cuda_runtime.h>
#include <cuda_bf16.h>
#include <cstdint>

// Problem constants
#define B_  64
#define C_  2048
#define HW_ 192            // 24 * 8
#define NCHUNK 8           // C chunks
#define CCHUNK (C_ / NCHUNK)   // 256 channels per chunk
#define NUM_IDS_ 751

// Scratch (no device allocation allowed; use __device__ globals)
__device__ float g_partial[B_ * NCHUNK * HW_];   // per-(b, chunk) partial heat
__device__ float g_heat[B_ * HW_];               // normalized heat

// ---------------------------------------------------------------------------
// pid loader: pids buffer may be int32 (64 ints) or int64 (64 longs).
// We only ever read the first 64 int32 words for detection (256 B, safe under
// both layouts). int64 layout => odd words are all 0 (values < 751 -> high
// word 0) ; int32 layout => odd words random in [0,751).
// ---------------------------------------------------------------------------
__device__ __forceinline__ int load_pid(const int* __restrict__ p32, int b)
{
    bool odd_all_zero = true;
    bool any_nonzero  = false;
    #pragma unroll
    for (int i = 0; i < 64; i += 2) {
        int lo = p32[i];
        int hi = p32[i + 1];
        if (hi != 0) odd_all_zero = false;
        if (lo != 0) any_nonzero = true;
    }
    const bool is64 = odd_all_zero && any_nonzero;
    int pid = is64 ? p32[2 * b] : p32[b];
    // guard against any remaining surprise (keeps us from crashing)
    if (pid < 0) pid = 0;
    if (pid >= NUM_IDS_) pid = NUM_IDS_ - 1;
    return pid;
}

// ---------------------------------------------------------------------------
// Kernel 1: partial heat. grid = (B_, NCHUNK), block = 192 threads.
// heat_partial[b][chunk][hw] = sum_{c in chunk} w[pid[b]][c] * f[b][c][hw]
// Each c-iteration: 192 threads read one contiguous 768B row -> coalesced.
// ---------------------------------------------------------------------------
__global__ void __launch_bounds__(HW_) heat_partial_kernel(
    const float* __restrict__ f,
    const float* __restrict__ w,
    const int*   __restrict__ pids32)
{
    const int b     = blockIdx.x;
    const int chunk = blockIdx.y;
    const int hw    = threadIdx.x;   // 0..191

    __shared__ float ws[CCHUNK];
    __shared__ int s_pid;

    if (threadIdx.x == 0)
        s_pid = load_pid(pids32, b);
    __syncthreads();

    const float* wrow = w + (size_t)s_pid * C_ + chunk * CCHUNK;
    for (int i = threadIdx.x; i < CCHUNK; i += HW_)
        ws[i] = wrow[i];
    __syncthreads();

    const float* fb = f + ((size_t)b * C_ + (size_t)chunk * CCHUNK) * HW_ + hw;

    float acc0 = 0.f, acc1 = 0.f, acc2 = 0.f, acc3 = 0.f;
    #pragma unroll 8
    for (int c = 0; c < CCHUNK; c += 4) {
        acc0 = fmaf(ws[c + 0], fb[(size_t)(c + 0) * HW_], acc0);
        acc1 = fmaf(ws[c + 1], fb[(size_t)(c + 1) * HW_], acc1);
        acc2 = fmaf(ws[c + 2], fb[(size_t)(c + 2) * HW_], acc2);
        acc3 = fmaf(ws[c + 3], fb[(size_t)(c + 3) * HW_], acc3);
    }
    g_partial[((size_t)b * NCHUNK + chunk) * HW_ + hw] = (acc0 + acc1) + (acc2 + acc3);
}

// ---------------------------------------------------------------------------
// Kernel 2: reduce partials, min/max-normalize per b. grid = B_, block = 192.
// ---------------------------------------------------------------------------
__global__ void __launch_bounds__(HW_) heat_norm_kernel()
{
    const int b  = blockIdx.x;
    const int hw = threadIdx.x;

    float s = 0.f;
    #pragma unroll
    for (int p = 0; p < NCHUNK; p++)
        s += g_partial[((size_t)b * NCHUNK + p) * HW_ + hw];

    // block min/max over 192 values (6 warps)
    float mn = s, mx = s;
    #pragma unroll
    for (int off = 16; off > 0; off >>= 1) {
        mn = fminf(mn, __shfl_down_sync(0xffffffffu, mn, off));
        mx = fmaxf(mx, __shfl_down_sync(0xffffffffu, mx, off));
    }
    __shared__ float smn[6], smx[6];
    __shared__ float bmn, bmx;
    const int warp = hw >> 5, lane = hw & 31;
    if (lane == 0) { smn[warp] = mn; smx[warp] = mx; }
    __syncthreads();
    if (hw == 0) {
        float m0 = smn[0], m1 = smx[0];
        #pragma unroll
        for (int i = 1; i < 6; i++) {
            m0 = fminf(m0, smn[i]);
            m1 = fmaxf(m1, smx[i]);
        }
        bmn = m0; bmx = m1;
    }
    __syncthreads();

    float h = s;
    if (bmx != 0.f)
        h = (s - bmn) / (bmx - bmn);
    g_heat[(size_t)b * HW_ + hw] = h;
}

// ---------------------------------------------------------------------------
// Kernel 3: out = f * heat[b][hw], float4-vectorized (HW_ % 4 == 0, so each
// float4 stays within one row and hw base is 4-aligned -> vector heat load).
// ---------------------------------------------------------------------------
__global__ void __launch_bounds__(256) scale_kernel(
    const float4* __restrict__ f4,
    float4* __restrict__ out4)
{
    const int i = blockIdx.x * blockDim.x + threadIdx.x;   // float4 index
    const int n4 = (B_ * C_ * HW_) / 4;                    // 6,291,456
    if (i >= n4) return;

    const int e  = i * 4;                 // element index (max 25.2M, fits int32)
    const int hw = e % HW_;               // 4-aligned
    const int b  = e / (C_ * HW_);

    const float4 hv = *reinterpret_cast<const float4*>(&g_heat[b * HW_ + hw]);
    float4 v = f4[i];
    v.x *= hv.x; v.y *= hv.y; v.z *= hv.z; v.w *= hv.w;
    out4[i] = v;
}

// ---------------------------------------------------------------------------
extern "C" void kernel_launch(void* const* d_in, const int* in_sizes, int n_in,
                              void* d_out, int out_size)
{
    // Resolve inputs by element count (robust to metadata ordering):
    //   features_map      : 64*2048*24*8 = 25,165,824
    //   classifier_weight : 751*2048    =  1,538,048
    //   pids              : 64
    const float* f = nullptr;
    const float* w = nullptr;
    const int*   p = nullptr;
    for (int i = 0; i < n_in; i++) {
        if      (in_sizes[i] == 25165824) f = (const float*)d_in[i];
        else if (in_sizes[i] == 1538048)  w = (const float*)d_in[i];
        else if (in_sizes[i] == 64)       p = (const int*)d_in[i];
    }
    float* out = (float*)d_out;

    heat_partial_kernel<<<dim3(B_, NCHUNK), HW_>>>(f, w, p);
    heat_norm_kernel<<<B_, HW_>>>();

    const int n4 = (B_ * C_ * HW_) / 4;                 // 6,291,456
    const int threads = 256;
    const int blocks = (n4 + threads - 1) / threads;    // 24576
    scale_kernel<<<blocks, threads>>>((const float4*)f, (float4*)out);
}

// round 3
// speedup vs baseline: 1.0657x; 1.0657x over previous
#include <cuda_runtime.h>
#include <cuda_bf16.h>
#include <cstdint>

// Problem constants
#define B_  64
#define C_  2048
#define HW_ 192            // 24 * 8
#define HW4_ 48            // HW_/4 float4s per row
#define NCHUNK 16          // C chunks
#define CCHUNK (C_ / NCHUNK)   // 128 channels per chunk
#define NPART (NCHUNK * 4)     // 64 partials per (b,hw)
#define NUM_IDS_ 751

// Scratch (__device__ globals; no allocation allowed)
__device__ float g_partial[B_ * NPART * HW_];    // [b][part][hw]  (3 MB)
__device__ float g_heat[B_ * HW_];               // normalized heat

// ---------------------------------------------------------------------------
// pid loader: pids buffer may be int32 (64 ints) or int64 (64 longs).
// Only the first 64 int32 words are read (256 B, safe under both layouts).
// int64 layout => odd words all 0 (values < 751); int32 => odd words random.
// ---------------------------------------------------------------------------
__device__ __forceinline__ int load_pid(const int* __restrict__ p32, int b)
{
    bool odd_all_zero = true;
    bool any_nonzero  = false;
    #pragma unroll
    for (int i = 0; i < 64; i += 2) {
        if (p32[i + 1] != 0) odd_all_zero = false;
        if (p32[i]     != 0) any_nonzero = true;
    }
    const bool is64 = odd_all_zero && any_nonzero;
    int pid = is64 ? p32[2 * b] : p32[b];
    if (pid < 0) pid = 0;
    if (pid >= NUM_IDS_) pid = NUM_IDS_ - 1;
    return pid;
}

// ---------------------------------------------------------------------------
// Kernel 1: partial heat with float4 row loads.
// grid = (B_, NCHUNK), block = 192 threads = 4 c-lanes x 48 float4-lanes.
// Thread (c_sub, q) accumulates float4 over c = c_sub, c_sub+4, ...
// partial[b][chunk*4 + c_sub][hw] = sum_{c in lane} w[pid][c] * f[b][c][hw]
// ---------------------------------------------------------------------------
__global__ void __launch_bounds__(HW_) heat_partial_kernel(
    const float4* __restrict__ f4,
    const float*  __restrict__ w,
    const int*    __restrict__ pids32)
{
    const int b     = blockIdx.x;
    const int chunk = blockIdx.y;
    const int tid   = threadIdx.x;
    const int c_sub = tid / HW4_;   // 0..3
    const int q     = tid % HW4_;   // 0..47 (float4 index within row)

    __shared__ float ws[CCHUNK];
    __shared__ int s_pid;

    if (tid == 0)
        s_pid = load_pid(pids32, b);
    __syncthreads();

    const float* wrow = w + (size_t)s_pid * C_ + chunk * CCHUNK;
    if (tid < CCHUNK)
        ws[tid] = wrow[tid];
    __syncthreads();

    // f4 row pointer: f[b][c0][*] as float4; row stride in float4s = HW4_
    const float4* fb = f4 + ((size_t)b * C_ + (size_t)chunk * CCHUNK) * HW4_ + q;

    float4 acc = make_float4(0.f, 0.f, 0.f, 0.f);
    #pragma unroll 8
    for (int c = c_sub; c < CCHUNK; c += 4) {
        const float4 v = fb[(size_t)c * HW4_];
        const float  s = ws[c];
        acc.x = fmaf(s, v.x, acc.x);
        acc.y = fmaf(s, v.y, acc.y);
        acc.z = fmaf(s, v.z, acc.z);
        acc.w = fmaf(s, v.w, acc.w);
    }

    const int part = chunk * 4 + c_sub;   // 0..63
    float4* gp4 = reinterpret_cast<float4*>(g_partial);
    gp4[((size_t)b * NPART + part) * HW4_ + q] = acc;
}

// ---------------------------------------------------------------------------
// Kernel 2: reduce 64 partials, min/max-normalize per b. grid = B_, block=192.
// ---------------------------------------------------------------------------
__global__ void __launch_bounds__(HW_) heat_norm_kernel()
{
    const int b  = blockIdx.x;
    const int hw = threadIdx.x;

    float s = 0.f;
    #pragma unroll
    for (int p = 0; p < NPART; p++)
        s += g_partial[((size_t)b * NPART + p) * HW_ + hw];

    // block min/max over 192 values (6 warps)
    float mn = s, mx = s;
    #pragma unroll
    for (int off = 16; off > 0; off >>= 1) {
        mn = fminf(mn, __shfl_down_sync(0xffffffffu, mn, off));
        mx = fmaxf(mx, __shfl_down_sync(0xffffffffu, mx, off));
    }
    __shared__ float smn[6], smx[6];
    __shared__ float bmn, bmx;
    const int warp = hw >> 5, lane = hw & 31;
    if (lane == 0) { smn[warp] = mn; smx[warp] = mx; }
    __syncthreads();
    if (hw == 0) {
        float m0 = smn[0], m1 = smx[0];
        #pragma unroll
        for (int i = 1; i < 6; i++) {
            m0 = fminf(m0, smn[i]);
            m1 = fmaxf(m1, smx[i]);
        }
        bmn = m0; bmx = m1;
    }
    __syncthreads();

    float h = s;
    if (bmx != 0.f)
        h = (s - bmn) / (bmx - bmn);
    g_heat[(size_t)b * HW_ + hw] = h;
}

// ---------------------------------------------------------------------------
// Kernel 3: out = f * heat[b][hw], float4 + ILP4.
// Each thread handles 4 coalesced float4s: idx, idx+bd, idx+2bd, idx+3bd.
// n4 = 6,291,456 float4s; grid = n4 / (256*4) = 6144 blocks (exact).
// ---------------------------------------------------------------------------
#define SC_ILP 4
__global__ void __launch_bounds__(256) scale_kernel(
    const float4* __restrict__ f4,
    float4* __restrict__ out4)
{
    const int base = blockIdx.x * (256 * SC_ILP) + threadIdx.x;

    float4 v[SC_ILP];
    float4 hv[SC_ILP];
    #pragma unroll
    for (int k = 0; k < SC_ILP; k++) {
        const int i  = base + k * 256;
        const int e  = i * 4;            // element index (max 25.2M, fits int32)
        const int hw = e % HW_;          // 4-aligned
        const int b  = e / (C_ * HW_);
        v[k]  = f4[i];
        hv[k] = *reinterpret_cast<const float4*>(&g_heat[b * HW_ + hw]);
    }
    #pragma unroll
    for (int k = 0; k < SC_ILP; k++) {
        const int i = base + k * 256;
        float4 r;
        r.x = v[k].x * hv[k].x;
        r.y = v[k].y * hv[k].y;
        r.z = v[k].z * hv[k].z;
        r.w = v[k].w * hv[k].w;
        out4[i] = r;
    }
}

// ---------------------------------------------------------------------------
extern "C" void kernel_launch(void* const* d_in, const int* in_sizes, int n_in,
                              void* d_out, int out_size)
{
    // Resolve inputs by element count:
    //   features_map      : 25,165,824
    //   classifier_weight :  1,538,048
    //   pids              : 64
    const float* f = nullptr;
    const float* w = nullptr;
    const int*   p = nullptr;
    for (int i = 0; i < n_in; i++) {
        if      (in_sizes[i] == 25165824) f = (const float*)d_in[i];
        else if (in_sizes[i] == 1538048)  w = (const float*)d_in[i];
        else if (in_sizes[i] == 64)       p = (const int*)d_in[i];
    }
    float* out = (float*)d_out;

    heat_partial_kernel<<<dim3(B_, NCHUNK), HW_>>>((const float4*)f, w, p);
    heat_norm_kernel<<<B_, HW_>>>();

    const int n4 = (B_ * C_ * HW_) / 4;                  // 6,291,456
    const int blocks = n4 / (256 * SC_ILP);              // 6144 (exact)
    scale_kernel<<<blocks, 256>>>((const float4*)f, (float4*)out);
}

// round 4
// speedup vs baseline: 1.0664x; 1.0006x over previous
#include <cuda_runtime.h>
#include <cuda_bf16.h>
#include <cstdint>

// Problem constants
#define B_  64
#define C_  2048
#define HW_ 192            // 24 * 8
#define HW4_ 48            // HW_/4 float4s per row
#define NCHUNK 32          // C chunks  (grid = 64*32 = 2048 blocks)
#define CCHUNK (C_ / NCHUNK)   // 64 channels per chunk
#define NPART (NCHUNK * 4)     // 128 partials per (b,hw)
#define NUM_IDS_ 751

// Scratch (__device__ globals; no allocation allowed)
__device__ float g_partial[B_ * NPART * HW_];    // [b][part][hw]  (6 MB)
__device__ float g_heat[B_ * HW_];               // normalized heat

// ---------------------------------------------------------------------------
// pid loader: pids buffer may be int32 (64 ints) or int64 (64 longs).
// Only the first 64 int32 words are read (256 B, safe under both layouts).
// int64 layout => odd words all 0 (values < 751); int32 => odd words random.
// ---------------------------------------------------------------------------
__device__ __forceinline__ int load_pid(const int* __restrict__ p32, int b)
{
    bool odd_all_zero = true;
    bool any_nonzero  = false;
    #pragma unroll
    for (int i = 0; i < 64; i += 2) {
        if (p32[i + 1] != 0) odd_all_zero = false;
        if (p32[i]     != 0) any_nonzero = true;
    }
    const bool is64 = odd_all_zero && any_nonzero;
    int pid = is64 ? p32[2 * b] : p32[b];
    if (pid < 0) pid = 0;
    if (pid >= NUM_IDS_) pid = NUM_IDS_ - 1;
    return pid;
}

// ---------------------------------------------------------------------------
// Kernel 1: partial heat with float4 row loads.
// grid = (B_, NCHUNK), block = 192 threads = 4 c-lanes x 48 float4-lanes.
// Thread (c_sub, q) accumulates float4 over c = c_sub, c_sub+4, ... (16 iters,
// fully unrolled -> 16 independent LDG.128 in flight per thread).
// ---------------------------------------------------------------------------
__global__ void __launch_bounds__(HW_) heat_partial_kernel(
    const float4* __restrict__ f4,
    const float*  __restrict__ w,
    const int*    __restrict__ pids32)
{
    const int b     = blockIdx.x;
    const int chunk = blockIdx.y;
    const int tid   = threadIdx.x;
    const int c_sub = tid / HW4_;   // 0..3
    const int q     = tid % HW4_;   // 0..47 (float4 index within row)

    __shared__ float ws[CCHUNK];
    __shared__ int s_pid;

    if (tid == 0)
        s_pid = load_pid(pids32, b);
    __syncthreads();

    const float* wrow = w + (size_t)s_pid * C_ + chunk * CCHUNK;
    if (tid < CCHUNK)
        ws[tid] = wrow[tid];
    __syncthreads();

    // f4 row pointer: f[b][c0][*] as float4; row stride in float4s = HW4_
    const float4* fb = f4 + ((size_t)b * C_ + (size_t)chunk * CCHUNK) * HW4_ + q;

    float4 acc = make_float4(0.f, 0.f, 0.f, 0.f);
    #pragma unroll
    for (int c = c_sub; c < CCHUNK; c += 4) {
        const float4 v = fb[(size_t)c * HW4_];
        const float  s = ws[c];
        acc.x = fmaf(s, v.x, acc.x);
        acc.y = fmaf(s, v.y, acc.y);
        acc.z = fmaf(s, v.z, acc.z);
        acc.w = fmaf(s, v.w, acc.w);
    }

    const int part = chunk * 4 + c_sub;   // 0..127
    float4* gp4 = reinterpret_cast<float4*>(g_partial);
    gp4[((size_t)b * NPART + part) * HW4_ + q] = acc;
}

// ---------------------------------------------------------------------------
// Kernel 2: reduce 128 partials, min/max-normalize per b. grid = B_, block=192.
// Partials are L2-resident (6 MB, just written).
// ---------------------------------------------------------------------------
__global__ void __launch_bounds__(HW_) heat_norm_kernel()
{
    const int b  = blockIdx.x;
    const int hw = threadIdx.x;

    float s0 = 0.f, s1 = 0.f, s2 = 0.f, s3 = 0.f;
    #pragma unroll
    for (int p = 0; p < NPART; p += 4) {
        s0 += g_partial[((size_t)b * NPART + p + 0) * HW_ + hw];
        s1 += g_partial[((size_t)b * NPART + p + 1) * HW_ + hw];
        s2 += g_partial[((size_t)b * NPART + p + 2) * HW_ + hw];
        s3 += g_partial[((size_t)b * NPART + p + 3) * HW_ + hw];
    }
    const float s = (s0 + s1) + (s2 + s3);

    // block min/max over 192 values (6 warps)
    float mn = s, mx = s;
    #pragma unroll
    for (int off = 16; off > 0; off >>= 1) {
        mn = fminf(mn, __shfl_down_sync(0xffffffffu, mn, off));
        mx = fmaxf(mx, __shfl_down_sync(0xffffffffu, mx, off));
    }
    __shared__ float smn[6], smx[6];
    __shared__ float bmn, bmx;
    const int warp = hw >> 5, lane = hw & 31;
    if (lane == 0) { smn[warp] = mn; smx[warp] = mx; }
    __syncthreads();
    if (hw == 0) {
        float m0 = smn[0], m1 = smx[0];
        #pragma unroll
        for (int i = 1; i < 6; i++) {
            m0 = fminf(m0, smn[i]);
            m1 = fmaxf(m1, smx[i]);
        }
        bmn = m0; bmx = m1;
    }
    __syncthreads();

    float h = s;
    if (bmx != 0.f)
        h = (s - bmn) / (bmx - bmn);
    g_heat[(size_t)b * HW_ + hw] = h;
}

// ---------------------------------------------------------------------------
// Kernel 3: out = f * heat[b][hw], float4 + ILP4. Already at the DRAM/LTS
// roofline (~6.7 TB/s) -- unchanged.
// ---------------------------------------------------------------------------
#define SC_ILP 4
__global__ void __launch_bounds__(256) scale_kernel(
    const float4* __restrict__ f4,
    float4* __restrict__ out4)
{
    const int base = blockIdx.x * (256 * SC_ILP) + threadIdx.x;

    float4 v[SC_ILP];
    float4 hv[SC_ILP];
    #pragma unroll
    for (int k = 0; k < SC_ILP; k++) {
        const int i  = base + k * 256;
        const int e  = i * 4;            // element index (max 25.2M, fits int32)
        const int hw = e % HW_;          // 4-aligned
        const int b  = e / (C_ * HW_);
        v[k]  = f4[i];
        hv[k] = *reinterpret_cast<const float4*>(&g_heat[b * HW_ + hw]);
    }
    #pragma unroll
    for (int k = 0; k < SC_ILP; k++) {
        const int i = base + k * 256;
        float4 r;
        r.x = v[k].x * hv[k].x;
        r.y = v[k].y * hv[k].y;
        r.z = v[k].z * hv[k].z;
        r.w = v[k].w * hv[k].w;
        out4[i] = r;
    }
}

// ---------------------------------------------------------------------------
extern "C" void kernel_launch(void* const* d_in, const int* in_sizes, int n_in,
                              void* d_out, int out_size)
{
    // Resolve inputs by element count:
    //   features_map      : 25,165,824
    //   classifier_weight :  1,538,048
    //   pids              : 64
    const float* f = nullptr;
    const float* w = nullptr;
    const int*   p = nullptr;
    for (int i = 0; i < n_in; i++) {
        if      (in_sizes[i] == 25165824) f = (const float*)d_in[i];
        else if (in_sizes[i] == 1538048)  w = (const float*)d_in[i];
        else if (in_sizes[i] == 64)       p = (const int*)d_in[i];
    }
    float* out = (float*)d_out;

    heat_partial_kernel<<<dim3(B_, NCHUNK), HW_>>>((const float4*)f, w, p);
    heat_norm_kernel<<<B_, HW_>>>();

    const int n4 = (B_ * C_ * HW_) / 4;                  // 6,291,456
    const int blocks = n4 / (256 * SC_ILP);              // 6144 (exact)
    scale_kernel<<<blocks, 256>>>((const float4*)f, (float4*)out);
}